// round 4
// baseline (speedup 1.0000x reference)
#include <cuda_runtime.h>

typedef unsigned long long ULL;

__device__ __forceinline__ ULL fma2(ULL a, ULL b, ULL c) {
    ULL d;
    asm("fma.rn.f32x2 %0, %1, %2, %3;" : "=l"(d) : "l"(a), "l"(b), "l"(c));
    return d;
}
__device__ __forceinline__ ULL dup2(float x) {
    ULL d;
    asm("mov.b64 %0, {%1, %1};" : "=l"(d) : "f"(x));
    return d;
}
__device__ __forceinline__ float2 unpk(ULL v) {
    float2 r;
    asm("mov.b64 {%0, %1}, %2;" : "=f"(r.x), "=f"(r.y) : "l"(v));
    return r;
}

#define N_TOT 8192
#define TN 8          // n's per attention block

// Scratch (static device globals — no allocation)
__device__ __align__(16) float2 g_ca2T[16 * 512];  // [k][p]
__device__ float g_c[N_TOT * 16];                  // pooled-projection output (N,16)

// ---------------------------------------------------------------------------
__global__ void pre_ca(const float* __restrict__ cx, const float* __restrict__ Wa1) {
    int idx = blockIdx.x * blockDim.x + threadIdx.x;   // 8192 = 512p * 16k
    int p = idx & 511, k = idx >> 9;
    float x0 = cx[p * 2 + 0], x1 = cx[p * 2 + 1];
    float c0 = x0 * Wa1[64 + 2 * k]     + x1 * Wa1[96 + 2 * k];
    float c1 = x0 * Wa1[64 + 2 * k + 1] + x1 * Wa1[96 + 2 * k + 1];
    g_ca2T[k * 512 + p] = make_float2(c0, c1);
}

// ---------------------------------------------------------------------------
// Attention: block handles TN consecutive n's; thread = p (P=512).
// ca staged in 64KB DYNAMIC smem (whole-block reuse); qa computed in-block;
// logits in registers; one batched epilogue.
__global__ __launch_bounds__(512) void attn_kernel(
    const float* __restrict__ r,
    const float* __restrict__ coeff_y,
    const float* __restrict__ Wa1,
    const float* __restrict__ Wa2,
    const float* __restrict__ Wa3,
    const float* __restrict__ Wp1, const float* __restrict__ bp1,
    const float* __restrict__ Wp2, const float* __restrict__ bp2)
{
    extern __shared__ __align__(16) float2 sCa[];   // [16][512] = 64KB dynamic

    __shared__ __align__(16) float sWa2[1024];
    __shared__ __align__(16) float2 sQa[TN][16];
    __shared__ __align__(8)  float sWa3[32];
    __shared__ float sMax[TN * 16];
    __shared__ float sGm[TN];
    __shared__ float sRed[16][TN][5];
    __shared__ float sPool[TN][5];
    __shared__ float sHp[TN][32];

    const int tid  = threadIdx.x;
    const int lane = tid & 31, warp = tid >> 5;
    const int n0 = blockIdx.x * TN;

    sWa2[tid]       = Wa2[tid];
    sWa2[tid + 512] = Wa2[tid + 512];
    if (tid < 32) sWa3[tid] = Wa3[tid];

    // copy ca tile into dynamic smem (8 float4 per thread)
    {
        float4* dst = reinterpret_cast<float4*>(sCa);
        const float4* src = reinterpret_cast<const float4*>(g_ca2T);
#pragma unroll
        for (int i = 0; i < 8; ++i) dst[tid + i * 512] = src[tid + i * 512];
    }
    // qa for this block's TN n's: qa[t][k] = r[n,0]*Wa1[0][...] + r[n,1]*Wa1[1][...]
    if (tid < TN * 16) {
        int t = tid >> 4, k = tid & 15;
        int n = n0 + t;
        float x0 = r[n * 4 + 0], x1 = r[n * 4 + 1];
        float q0 = x0 * Wa1[2 * k]     + x1 * Wa1[32 + 2 * k];
        float q1 = x0 * Wa1[2 * k + 1] + x1 * Wa1[32 + 2 * k + 1];
        sQa[t][k] = make_float2(q0, q1);
    }
    __syncthreads();

    float logits[TN];

#pragma unroll 1
    for (int t = 0; t < TN; ++t) {
        const float4* qa4 = reinterpret_cast<const float4*>(sQa[t]);

        ULL acc[16];
#pragma unroll
        for (int q = 0; q < 16; ++q) acc[q] = 0ull;

#pragma unroll
        for (int k2 = 0; k2 < 8; ++k2) {
            float4 qa = qa4[k2];                 // broadcast LDS
            float2 ca0 = sCa[(2 * k2) * 512 + tid];
            float2 ca1 = sCa[(2 * k2 + 1) * 512 + tid];
            {   // k = 2*k2
                int k = 2 * k2;
                ULL dlo = dup2(fmaxf(qa.x + ca0.x, 0.f));
                ULL dhi = dup2(fmaxf(qa.y + ca0.y, 0.f));
                const ulonglong2* r0 = reinterpret_cast<const ulonglong2*>(sWa2 + 64 * k);
#pragma unroll
                for (int q = 0; q < 8; ++q) {
                    ulonglong2 w0 = r0[q];
                    ulonglong2 w1 = r0[q + 8];
                    acc[2 * q]     = fma2(dlo, w0.x, acc[2 * q]);
                    acc[2 * q + 1] = fma2(dlo, w0.y, acc[2 * q + 1]);
                    acc[2 * q]     = fma2(dhi, w1.x, acc[2 * q]);
                    acc[2 * q + 1] = fma2(dhi, w1.y, acc[2 * q + 1]);
                }
            }
            {   // k = 2*k2+1
                int k = 2 * k2 + 1;
                ULL dlo = dup2(fmaxf(qa.z + ca1.x, 0.f));
                ULL dhi = dup2(fmaxf(qa.w + ca1.y, 0.f));
                const ulonglong2* r0 = reinterpret_cast<const ulonglong2*>(sWa2 + 64 * k);
#pragma unroll
                for (int q = 0; q < 8; ++q) {
                    ulonglong2 w0 = r0[q];
                    ulonglong2 w1 = r0[q + 8];
                    acc[2 * q]     = fma2(dlo, w0.x, acc[2 * q]);
                    acc[2 * q + 1] = fma2(dlo, w0.y, acc[2 * q + 1]);
                    acc[2 * q]     = fma2(dhi, w1.x, acc[2 * q]);
                    acc[2 * q + 1] = fma2(dhi, w1.y, acc[2 * q + 1]);
                }
            }
        }

        float logit = 0.f;
#pragma unroll
        for (int q = 0; q < 16; ++q) {
            float2 a = unpk(acc[q]);
            float2 w = reinterpret_cast<const float2*>(sWa3)[q];
            logit += fmaxf(a.x, 0.f) * w.x + fmaxf(a.y, 0.f) * w.y;
        }
        logits[t] = logit;

        float m = logit;
#pragma unroll
        for (int off = 16; off; off >>= 1)
            m = fmaxf(m, __shfl_xor_sync(0xffffffffu, m, off));
        if (lane == 0) sMax[t * 16 + warp] = m;
    }
    __syncthreads();

    if (tid < TN) {
        float gm = sMax[tid * 16];
#pragma unroll
        for (int w = 1; w < 16; ++w) gm = fmaxf(gm, sMax[tid * 16 + w]);
        sGm[tid] = gm;
    }
    __syncthreads();

    const float4 cy = reinterpret_cast<const float4*>(coeff_y)[tid];

#pragma unroll 1
    for (int t = 0; t < TN; ++t) {
        float e = __expf(logits[t] - sGm[t]);
        float v0 = e, v1 = e * cy.x, v2 = e * cy.y, v3 = e * cy.z, v4 = e * cy.w;
#pragma unroll
        for (int off = 16; off; off >>= 1) {
            v0 += __shfl_xor_sync(0xffffffffu, v0, off);
            v1 += __shfl_xor_sync(0xffffffffu, v1, off);
            v2 += __shfl_xor_sync(0xffffffffu, v2, off);
            v3 += __shfl_xor_sync(0xffffffffu, v3, off);
            v4 += __shfl_xor_sync(0xffffffffu, v4, off);
        }
        if (lane == 0) {
            sRed[warp][t][0] = v0; sRed[warp][t][1] = v1; sRed[warp][t][2] = v2;
            sRed[warp][t][3] = v3; sRed[warp][t][4] = v4;
        }
    }
    __syncthreads();
    if (tid < TN * 5) {
        int t = tid / 5, j = tid % 5;
        float s = 0.f;
#pragma unroll
        for (int w = 0; w < 16; ++w) s += sRed[w][t][j];
        sPool[t][j] = s;
    }
    __syncthreads();

    if (tid < TN * 32) {
        int t = tid >> 5, j = tid & 31;
        float inv = 1.f / sPool[t][0];
        float a0 = sPool[t][1] * inv, a1 = sPool[t][2] * inv;
        float a2 = sPool[t][3] * inv, a3 = sPool[t][4] * inv;
        float hp = bp1[j] + a0 * Wp1[j] + a1 * Wp1[32 + j]
                          + a2 * Wp1[64 + j] + a3 * Wp1[96 + j];
        sHp[t][j] = fmaxf(hp, 0.f);
    }
    __syncthreads();
    if (tid < TN * 16) {
        int t = tid >> 4, j = tid & 15;
        float cv = bp2[j];
#pragma unroll
        for (int k2 = 0; k2 < 32; ++k2) cv += sHp[t][k2] * Wp2[k2 * 16 + j];
        g_c[(n0 + t) * 16 + j] = cv;
    }
}

// ---------------------------------------------------------------------------
// Gating: block = 16 rows, 256 threads, grid 512.
// Stage B: warp w -> rows {2w,2w+1}; lane -> 8 j's; depth-2 rotated prefetch.
__global__ __launch_bounds__(256) void gate_kernel(
    const float* __restrict__ r, const float* __restrict__ rp,
    const float* __restrict__ Wg1, const float* __restrict__ bg1,
    const float* __restrict__ Wg2, const float* __restrict__ bg2,
    const float* __restrict__ Wg3, const float* __restrict__ bg3,
    float* __restrict__ out)
{
    __shared__ float sX[16][25];
    __shared__ __align__(8) float sG1[256 * 16];   // [k][row]

    const int tid  = threadIdx.x;
    const int lane = tid & 31, warp = tid >> 5;
    const int n0 = blockIdx.x * 16;

    for (int idx = tid; idx < 16 * 24; idx += 256) {
        int row = idx / 24, j = idx % 24;
        int n = n0 + row;
        float v = (j < 4) ? r[n * 4 + j]
                : (j < 8) ? rp[n * 4 + (j - 4)]
                          : g_c[n * 16 + (j - 8)];
        sX[row][j] = v;
    }
    __syncthreads();

    // Stage A: warp w -> k in [32w, 32w+32); lane -> (row = lane&15, khalf = lane>>4)
    {
        const int row = lane & 15, khalf = lane >> 4;
        float x[24];
#pragma unroll
        for (int j = 0; j < 24; ++j) x[j] = sX[row][j];
        const int kbase = warp * 32 + khalf;
#pragma unroll 4
        for (int kk = 0; kk < 16; ++kk) {
            int k = kbase + 2 * kk;
            float a = bg1[k];
#pragma unroll
            for (int j = 0; j < 24; ++j) a += x[j] * Wg1[j * 256 + k];
            sG1[k * 16 + row] = fmaxf(a, 0.f);
        }
    }
    __syncthreads();

    // Stage B
    const int jb = lane * 8;
    const int r2 = warp * 2;

    ULL bj[4];
    {
        const ulonglong2* b = reinterpret_cast<const ulonglong2*>(bg2 + jb);
        ulonglong2 b0 = b[0], b1 = b[1];
        bj[0] = b0.x; bj[1] = b0.y; bj[2] = b1.x; bj[3] = b1.y;
    }
    ULL acc[2][4];
#pragma unroll
    for (int i = 0; i < 2; ++i)
#pragma unroll
        for (int q = 0; q < 4; ++q) acc[i][q] = bj[q];

    const ulonglong2* wrow = reinterpret_cast<const ulonglong2*>(Wg2 + jb); // +64 per k
    float2 g = *reinterpret_cast<const float2*>(sG1 + r2);
    ulonglong2 wA = wrow[0], wB = wrow[1];

#pragma unroll 5
    for (int k = 0; k < 255; ++k) {
        float2 gn = *reinterpret_cast<const float2*>(sG1 + (k + 1) * 16 + r2);
        ulonglong2 wAn = wrow[(k + 1) * 64];
        ulonglong2 wBn = wrow[(k + 1) * 64 + 1];
        ULL d0 = dup2(g.x), d1 = dup2(g.y);
        acc[0][0] = fma2(d0, wA.x, acc[0][0]);
        acc[0][1] = fma2(d0, wA.y, acc[0][1]);
        acc[0][2] = fma2(d0, wB.x, acc[0][2]);
        acc[0][3] = fma2(d0, wB.y, acc[0][3]);
        acc[1][0] = fma2(d1, wA.x, acc[1][0]);
        acc[1][1] = fma2(d1, wA.y, acc[1][1]);
        acc[1][2] = fma2(d1, wB.x, acc[1][2]);
        acc[1][3] = fma2(d1, wB.y, acc[1][3]);
        g = gn; wA = wAn; wB = wBn;
    }
    {   // k = 255 tail
        ULL d0 = dup2(g.x), d1 = dup2(g.y);
        acc[0][0] = fma2(d0, wA.x, acc[0][0]);
        acc[0][1] = fma2(d0, wA.y, acc[0][1]);
        acc[0][2] = fma2(d0, wB.x, acc[0][2]);
        acc[0][3] = fma2(d0, wB.y, acc[0][3]);
        acc[1][0] = fma2(d1, wA.x, acc[1][0]);
        acc[1][1] = fma2(d1, wA.y, acc[1][1]);
        acc[1][2] = fma2(d1, wB.x, acc[1][2]);
        acc[1][3] = fma2(d1, wB.y, acc[1][3]);
    }

    float2 w3[4];
    {
        const float2* w3p = reinterpret_cast<const float2*>(Wg3 + jb);
        w3[0] = w3p[0]; w3[1] = w3p[1]; w3[2] = w3p[2]; w3[3] = w3p[3];
    }
    float part[2];
#pragma unroll
    for (int i = 0; i < 2; ++i) {
        float s = 0.f;
#pragma unroll
        for (int q = 0; q < 4; ++q) {
            float2 a = unpk(acc[i][q]);
            s += fmaxf(a.x, 0.f) * w3[q].x + fmaxf(a.y, 0.f) * w3[q].y;
        }
        part[i] = s;
    }
#pragma unroll
    for (int off = 16; off; off >>= 1) {
        part[0] += __shfl_xor_sync(0xffffffffu, part[0], off);
        part[1] += __shfl_xor_sync(0xffffffffu, part[1], off);
    }
    if (lane == 0) {
        float b3 = bg3[0];
        out[n0 + r2 + 0] = __expf(part[0] + b3);
        out[n0 + r2 + 1] = __expf(part[1] + b3);
    }
}

// ---------------------------------------------------------------------------
extern "C" void kernel_launch(void* const* d_in, const int* in_sizes, int n_in,
                              void* d_out, int out_size) {
    (void)in_sizes; (void)n_in; (void)out_size;
    const float* r   = (const float*)d_in[0];
    const float* rp  = (const float*)d_in[1];
    const float* cx  = (const float*)d_in[2];
    const float* cy  = (const float*)d_in[3];
    const float* Wa1 = (const float*)d_in[4];
    const float* Wa2 = (const float*)d_in[5];
    const float* Wa3 = (const float*)d_in[6];
    const float* Wp1 = (const float*)d_in[7];
    const float* bp1 = (const float*)d_in[8];
    const float* Wp2 = (const float*)d_in[9];
    const float* bp2 = (const float*)d_in[10];
    const float* Wg1 = (const float*)d_in[11];
    const float* bg1 = (const float*)d_in[12];
    const float* Wg2 = (const float*)d_in[13];
    const float* bg2 = (const float*)d_in[14];
    const float* Wg3 = (const float*)d_in[15];
    const float* bg3 = (const float*)d_in[16];
    float* out = (float*)d_out;

    const int dynSmem = 16 * 512 * sizeof(float2);   // 64KB
    cudaFuncSetAttribute(attn_kernel, cudaFuncAttributeMaxDynamicSharedMemorySize, dynSmem);

    pre_ca<<<16, 512>>>(cx, Wa1);
    attn_kernel<<<N_TOT / TN, 512, dynSmem>>>(r, cy, Wa1, Wa2, Wa3, Wp1, bp1, Wp2, bp2);
    gate_kernel<<<N_TOT / 16, 256>>>(r, rp, Wg1, bg1, Wg2, bg2, Wg3, bg3, out);
}

// round 5
// speedup vs baseline: 10.8567x; 10.8567x over previous
#include <cuda_runtime.h>

typedef unsigned long long ULL;

__device__ __forceinline__ ULL fma2(ULL a, ULL b, ULL c) {
    ULL d;
    asm("fma.rn.f32x2 %0, %1, %2, %3;" : "=l"(d) : "l"(a), "l"(b), "l"(c));
    return d;
}
__device__ __forceinline__ ULL dup2(float x) {
    ULL d;
    asm("mov.b64 %0, {%1, %1};" : "=l"(d) : "f"(x));
    return d;
}
__device__ __forceinline__ float2 unpk(ULL v) {
    float2 r;
    asm("mov.b64 {%0, %1}, %2;" : "=f"(r.x), "=f"(r.y) : "l"(v));
    return r;
}

#define N_TOT 8192
#define TN 8          // n's per attention block

// Scratch (static device globals — no allocation)
__device__ float2 g_ca2T[16 * 512];    // [k][p] : (ca[p][2k], ca[p][2k+1])
__device__ float2 g_qa2[N_TOT * 16];   // [n][k] : (qa[n][2k], qa[n][2k+1])
__device__ float  g_c[N_TOT * 16];     // pooled-projection output c (N,16)

// ---------------------------------------------------------------------------
__global__ void pre_ca(const float* __restrict__ cx, const float* __restrict__ Wa1) {
    int idx = blockIdx.x * blockDim.x + threadIdx.x;   // 8192 = 512p * 16k
    int p = idx & 511, k = idx >> 9;
    float x0 = cx[p * 2 + 0], x1 = cx[p * 2 + 1];
    float c0 = x0 * Wa1[64 + 2 * k]     + x1 * Wa1[96 + 2 * k];
    float c1 = x0 * Wa1[64 + 2 * k + 1] + x1 * Wa1[96 + 2 * k + 1];
    g_ca2T[k * 512 + p] = make_float2(c0, c1);
}

__global__ void pre_qa(const float* __restrict__ r, const float* __restrict__ Wa1) {
    int idx = blockIdx.x * blockDim.x + threadIdx.x;   // 131072 = 8192n * 16k
    int n = idx >> 4, k = idx & 15;
    float x0 = r[n * 4 + 0], x1 = r[n * 4 + 1];
    float q0 = x0 * Wa1[2 * k]     + x1 * Wa1[32 + 2 * k];
    float q1 = x0 * Wa1[2 * k + 1] + x1 * Wa1[32 + 2 * k + 1];
    g_qa2[n * 16 + k] = make_float2(q0, q1);
}

// ---------------------------------------------------------------------------
// Attention (round-1 proven structure): per block, TN consecutive n's;
// thread p = threadIdx.x (P=512). Per-t epilogue.
__global__ __launch_bounds__(512) void attn_kernel(
    const float* __restrict__ coeff_y,
    const float* __restrict__ Wa2,
    const float* __restrict__ Wa3,
    const float* __restrict__ Wp1, const float* __restrict__ bp1,
    const float* __restrict__ Wp2, const float* __restrict__ bp2)
{
    __shared__ __align__(16) float sWa2[1024];
    __shared__ float sMax[16];
    __shared__ float sRed[16][5];
    __shared__ float sPool[5];
    __shared__ float sHp[32];

    const int tid  = threadIdx.x;
    const int lane = tid & 31, warp = tid >> 5;

    sWa2[tid]       = Wa2[tid];
    sWa2[tid + 512] = Wa2[tid + 512];
    const float4 cy = reinterpret_cast<const float4*>(coeff_y)[tid];
    const int n0 = blockIdx.x * TN;
    __syncthreads();

    for (int t = 0; t < TN; ++t) {
        const int n = n0 + t;

        ULL acc[16];
#pragma unroll
        for (int q = 0; q < 16; ++q) acc[q] = 0ull;

#pragma unroll
        for (int k = 0; k < 16; ++k) {
            float2 ca = g_ca2T[k * 512 + tid];   // coalesced, L1-hot
            float2 qa = g_qa2[n * 16 + k];       // broadcast
            ULL dlo = dup2(fmaxf(qa.x + ca.x, 0.f));   // h1[2k]
            ULL dhi = dup2(fmaxf(qa.y + ca.y, 0.f));   // h1[2k+1]
            const ulonglong2* r0 = reinterpret_cast<const ulonglong2*>(sWa2 + 64 * k);
#pragma unroll
            for (int q = 0; q < 8; ++q) {
                ulonglong2 w0 = r0[q];       // Wa2 row 2k,   cols [4q..4q+3]
                ulonglong2 w1 = r0[q + 8];   // Wa2 row 2k+1, cols [4q..4q+3]
                acc[2 * q]     = fma2(dlo, w0.x, acc[2 * q]);
                acc[2 * q + 1] = fma2(dlo, w0.y, acc[2 * q + 1]);
                acc[2 * q]     = fma2(dhi, w1.x, acc[2 * q]);
                acc[2 * q + 1] = fma2(dhi, w1.y, acc[2 * q + 1]);
            }
        }

        float logit = 0.f;
#pragma unroll
        for (int q = 0; q < 16; ++q) {
            float2 a = unpk(acc[q]);
            float2 w = reinterpret_cast<const float2*>(Wa3)[q];
            logit += fmaxf(a.x, 0.f) * w.x + fmaxf(a.y, 0.f) * w.y;
        }

        // --- softmax over 512 threads ---
        float m = logit;
#pragma unroll
        for (int off = 16; off; off >>= 1)
            m = fmaxf(m, __shfl_xor_sync(0xffffffffu, m, off));
        if (lane == 0) sMax[warp] = m;
        __syncthreads();
        float gm = sMax[0];
#pragma unroll
        for (int w = 1; w < 16; ++w) gm = fmaxf(gm, sMax[w]);

        float e = __expf(logit - gm);
        float v0 = e, v1 = e * cy.x, v2 = e * cy.y, v3 = e * cy.z, v4 = e * cy.w;
#pragma unroll
        for (int off = 16; off; off >>= 1) {
            v0 += __shfl_xor_sync(0xffffffffu, v0, off);
            v1 += __shfl_xor_sync(0xffffffffu, v1, off);
            v2 += __shfl_xor_sync(0xffffffffu, v2, off);
            v3 += __shfl_xor_sync(0xffffffffu, v3, off);
            v4 += __shfl_xor_sync(0xffffffffu, v4, off);
        }
        if (lane == 0) {
            sRed[warp][0] = v0; sRed[warp][1] = v1; sRed[warp][2] = v2;
            sRed[warp][3] = v3; sRed[warp][4] = v4;
        }
        __syncthreads();
        if (tid < 5) {
            float s = 0.f;
#pragma unroll
            for (int w = 0; w < 16; ++w) s += sRed[w][tid];
            sPool[tid] = s;
        }
        __syncthreads();

        // --- pooled projection: c = relu(ao@Wp1+bp1)@Wp2+bp2 ---
        if (tid < 32) {
            float inv = 1.f / sPool[0];
            float a0 = sPool[1] * inv, a1 = sPool[2] * inv;
            float a2 = sPool[3] * inv, a3 = sPool[4] * inv;
            float hp = bp1[tid] + a0 * Wp1[tid] + a1 * Wp1[32 + tid]
                                + a2 * Wp1[64 + tid] + a3 * Wp1[96 + tid];
            sHp[tid] = fmaxf(hp, 0.f);
        }
        __syncthreads();
        if (tid < 16) {
            float cv = bp2[tid];
#pragma unroll
            for (int k2 = 0; k2 < 32; ++k2) cv += sHp[k2] * Wp2[k2 * 16 + tid];
            g_c[n * 16 + tid] = cv;
        }
        __syncthreads();
    }
}

// ---------------------------------------------------------------------------
// Gating: block = 16 rows, 256 threads, grid 512.
// Stage B: warp w -> rows {2w,2w+1}; lane -> 8 j's; depth-2 rotated prefetch.
__global__ __launch_bounds__(256) void gate_kernel(
    const float* __restrict__ r, const float* __restrict__ rp,
    const float* __restrict__ Wg1, const float* __restrict__ bg1,
    const float* __restrict__ Wg2, const float* __restrict__ bg2,
    const float* __restrict__ Wg3, const float* __restrict__ bg3,
    float* __restrict__ out)
{
    __shared__ float sX[16][25];
    __shared__ __align__(8) float sG1[256 * 16];   // [k][row]

    const int tid  = threadIdx.x;
    const int lane = tid & 31, warp = tid >> 5;
    const int n0 = blockIdx.x * 16;

    for (int idx = tid; idx < 16 * 24; idx += 256) {
        int row = idx / 24, j = idx % 24;
        int n = n0 + row;
        float v = (j < 4) ? r[n * 4 + j]
                : (j < 8) ? rp[n * 4 + (j - 4)]
                          : g_c[n * 16 + (j - 8)];
        sX[row][j] = v;
    }
    __syncthreads();

    // Stage A: warp w -> k in [32w, 32w+32); lane -> (row = lane&15, khalf = lane>>4)
    {
        const int row = lane & 15, khalf = lane >> 4;
        float x[24];
#pragma unroll
        for (int j = 0; j < 24; ++j) x[j] = sX[row][j];
        const int kbase = warp * 32 + khalf;
#pragma unroll 4
        for (int kk = 0; kk < 16; ++kk) {
            int k = kbase + 2 * kk;
            float a = bg1[k];
#pragma unroll
            for (int j = 0; j < 24; ++j) a += x[j] * Wg1[j * 256 + k];
            sG1[k * 16 + row] = fmaxf(a, 0.f);
        }
    }
    __syncthreads();

    // Stage B
    const int jb = lane * 8;
    const int r2 = warp * 2;

    ULL bj[4];
    {
        const ulonglong2* b = reinterpret_cast<const ulonglong2*>(bg2 + jb);
        ulonglong2 b0 = b[0], b1 = b[1];
        bj[0] = b0.x; bj[1] = b0.y; bj[2] = b1.x; bj[3] = b1.y;
    }
    ULL acc[2][4];
#pragma unroll
    for (int i = 0; i < 2; ++i)
#pragma unroll
        for (int q = 0; q < 4; ++q) acc[i][q] = bj[q];

    const ulonglong2* wrow = reinterpret_cast<const ulonglong2*>(Wg2 + jb); // +64 per k
    float2 g = *reinterpret_cast<const float2*>(sG1 + r2);
    ulonglong2 wA = wrow[0], wB = wrow[1];

#pragma unroll 5
    for (int k = 0; k < 255; ++k) {
        float2 gn = *reinterpret_cast<const float2*>(sG1 + (k + 1) * 16 + r2);
        ulonglong2 wAn = wrow[(k + 1) * 64];
        ulonglong2 wBn = wrow[(k + 1) * 64 + 1];
        ULL d0 = dup2(g.x), d1 = dup2(g.y);
        acc[0][0] = fma2(d0, wA.x, acc[0][0]);
        acc[0][1] = fma2(d0, wA.y, acc[0][1]);
        acc[0][2] = fma2(d0, wB.x, acc[0][2]);
        acc[0][3] = fma2(d0, wB.y, acc[0][3]);
        acc[1][0] = fma2(d1, wA.x, acc[1][0]);
        acc[1][1] = fma2(d1, wA.y, acc[1][1]);
        acc[1][2] = fma2(d1, wB.x, acc[1][2]);
        acc[1][3] = fma2(d1, wB.y, acc[1][3]);
        g = gn; wA = wAn; wB = wBn;
    }
    {   // k = 255 tail
        ULL d0 = dup2(g.x), d1 = dup2(g.y);
        acc[0][0] = fma2(d0, wA.x, acc[0][0]);
        acc[0][1] = fma2(d0, wA.y, acc[0][1]);
        acc[0][2] = fma2(d0, wB.x, acc[0][2]);
        acc[0][3] = fma2(d0, wB.y, acc[0][3]);
        acc[1][0] = fma2(d1, wA.x, acc[1][0]);
        acc[1][1] = fma2(d1, wA.y, acc[1][1]);
        acc[1][2] = fma2(d1, wB.x, acc[1][2]);
        acc[1][3] = fma2(d1, wB.y, acc[1][3]);
    }

    float2 w3[4];
    {
        const float2* w3p = reinterpret_cast<const float2*>(Wg3 + jb);
        w3[0] = w3p[0]; w3[1] = w3p[1]; w3[2] = w3p[2]; w3[3] = w3p[3];
    }
    float part[2];
#pragma unroll
    for (int i = 0; i < 2; ++i) {
        float s = 0.f;
#pragma unroll
        for (int q = 0; q < 4; ++q) {
            float2 a = unpk(acc[i][q]);
            s += fmaxf(a.x, 0.f) * w3[q].x + fmaxf(a.y, 0.f) * w3[q].y;
        }
        part[i] = s;
    }
#pragma unroll
    for (int off = 16; off; off >>= 1) {
        part[0] += __shfl_xor_sync(0xffffffffu, part[0], off);
        part[1] += __shfl_xor_sync(0xffffffffu, part[1], off);
    }
    if (lane == 0) {
        float b3 = bg3[0];
        out[n0 + r2 + 0] = __expf(part[0] + b3);
        out[n0 + r2 + 1] = __expf(part[1] + b3);
    }
}

// ---------------------------------------------------------------------------
extern "C" void kernel_launch(void* const* d_in, const int* in_sizes, int n_in,
                              void* d_out, int out_size) {
    (void)in_sizes; (void)n_in; (void)out_size;
    const float* r   = (const float*)d_in[0];
    const float* rp  = (const float*)d_in[1];
    const float* cx  = (const float*)d_in[2];
    const float* cy  = (const float*)d_in[3];
    const float* Wa1 = (const float*)d_in[4];
    const float* Wa2 = (const float*)d_in[5];
    const float* Wa3 = (const float*)d_in[6];
    const float* Wp1 = (const float*)d_in[7];
    const float* bp1 = (const float*)d_in[8];
    const float* Wp2 = (const float*)d_in[9];
    const float* bp2 = (const float*)d_in[10];
    const float* Wg1 = (const float*)d_in[11];
    const float* bg1 = (const float*)d_in[12];
    const float* Wg2 = (const float*)d_in[13];
    const float* bg2 = (const float*)d_in[14];
    const float* Wg3 = (const float*)d_in[15];
    const float* bg3 = (const float*)d_in[16];
    float* out = (float*)d_out;

    pre_ca<<<16, 512>>>(cx, Wa1);
    pre_qa<<<512, 256>>>(r, Wa1);
    attn_kernel<<<N_TOT / TN, 512>>>(cy, Wa2, Wa3, Wp1, bp1, Wp2, bp2);
    gate_kernel<<<N_TOT / 16, 256>>>(r, rp, Wg1, bg1, Wg2, bg2, Wg3, bg3, out);
}

// round 6
// speedup vs baseline: 16.1281x; 1.4855x over previous
#include <cuda_runtime.h>

typedef unsigned long long ULL;

__device__ __forceinline__ ULL fma2(ULL a, ULL b, ULL c) {
    ULL d;
    asm("fma.rn.f32x2 %0, %1, %2, %3;" : "=l"(d) : "l"(a), "l"(b), "l"(c));
    return d;
}
__device__ __forceinline__ ULL dup2(float x) {
    ULL d;
    asm("mov.b64 %0, {%1, %1};" : "=l"(d) : "f"(x));
    return d;
}
__device__ __forceinline__ float2 unpk(ULL v) {
    float2 r;
    asm("mov.b64 {%0, %1}, %2;" : "=f"(r.x), "=f"(r.y) : "l"(v));
    return r;
}

#define N_TOT 8192
#define TN 8          // n's per attention block (processed as 4 pairs)

// Scratch (static device globals — no allocation)
__device__ float2 g_ca2T[16 * 512];    // [k][p]
__device__ float2 g_qa2[N_TOT * 16];   // [n][k]
__device__ float  g_c[N_TOT * 16];     // pooled-projection output c (N,16)

// ---------------------------------------------------------------------------
__global__ void pre_ca(const float* __restrict__ cx, const float* __restrict__ Wa1) {
    int idx = blockIdx.x * blockDim.x + threadIdx.x;   // 8192 = 512p * 16k
    int p = idx & 511, k = idx >> 9;
    float x0 = cx[p * 2 + 0], x1 = cx[p * 2 + 1];
    float c0 = x0 * Wa1[64 + 2 * k]     + x1 * Wa1[96 + 2 * k];
    float c1 = x0 * Wa1[64 + 2 * k + 1] + x1 * Wa1[96 + 2 * k + 1];
    g_ca2T[k * 512 + p] = make_float2(c0, c1);
}

__global__ void pre_qa(const float* __restrict__ r, const float* __restrict__ Wa1) {
    int idx = blockIdx.x * blockDim.x + threadIdx.x;   // 131072 = 8192n * 16k
    int n = idx >> 4, k = idx & 15;
    float x0 = r[n * 4 + 0], x1 = r[n * 4 + 1];
    float q0 = x0 * Wa1[2 * k]     + x1 * Wa1[32 + 2 * k];
    float q1 = x0 * Wa1[2 * k + 1] + x1 * Wa1[32 + 2 * k + 1];
    g_qa2[n * 16 + k] = make_float2(q0, q1);
}

// ---------------------------------------------------------------------------
// Attention: block handles TN consecutive n's as 4 PAIRS; thread = p.
// Wa2 smem broadcasts amortize over the pair (64 FFMA2 per 16 LDS.128).
__global__ __launch_bounds__(512) void attn_kernel(
    const float* __restrict__ coeff_y,
    const float* __restrict__ Wa2,
    const float* __restrict__ Wa3,
    const float* __restrict__ Wp1, const float* __restrict__ bp1,
    const float* __restrict__ Wp2, const float* __restrict__ bp2)
{
    __shared__ __align__(16) float sWa2[1024];
    __shared__ float sMax[16];
    __shared__ float sRed[16][5];
    __shared__ float sPool[5];
    __shared__ float sHp[32];

    const int tid  = threadIdx.x;
    const int lane = tid & 31, warp = tid >> 5;

    sWa2[tid]       = Wa2[tid];
    sWa2[tid + 512] = Wa2[tid + 512];
    const float4 cy = reinterpret_cast<const float4*>(coeff_y)[tid];
    const int n0 = blockIdx.x * TN;
    __syncthreads();

#pragma unroll 1
    for (int t2 = 0; t2 < TN / 2; ++t2) {
        const int n = n0 + 2 * t2;

        ULL acc0[16], acc1[16];
#pragma unroll
        for (int q = 0; q < 16; ++q) { acc0[q] = 0ull; acc1[q] = 0ull; }

#pragma unroll
        for (int k = 0; k < 16; ++k) {
            float2 ca  = g_ca2T[k * 512 + tid];    // coalesced, L1-hot
            float2 qa0 = g_qa2[n * 16 + k];        // broadcast
            float2 qa1 = g_qa2[(n + 1) * 16 + k];  // broadcast
            ULL a_lo = dup2(fmaxf(qa0.x + ca.x, 0.f));
            ULL a_hi = dup2(fmaxf(qa0.y + ca.y, 0.f));
            ULL b_lo = dup2(fmaxf(qa1.x + ca.x, 0.f));
            ULL b_hi = dup2(fmaxf(qa1.y + ca.y, 0.f));
            const ulonglong2* r0 = reinterpret_cast<const ulonglong2*>(sWa2 + 64 * k);
#pragma unroll
            for (int q = 0; q < 8; ++q) {
                ulonglong2 w0 = r0[q];       // Wa2 row 2k,   cols [4q..4q+3]
                ulonglong2 w1 = r0[q + 8];   // Wa2 row 2k+1, cols [4q..4q+3]
                acc0[2 * q]     = fma2(a_lo, w0.x, acc0[2 * q]);
                acc0[2 * q + 1] = fma2(a_lo, w0.y, acc0[2 * q + 1]);
                acc1[2 * q]     = fma2(b_lo, w0.x, acc1[2 * q]);
                acc1[2 * q + 1] = fma2(b_lo, w0.y, acc1[2 * q + 1]);
                acc0[2 * q]     = fma2(a_hi, w1.x, acc0[2 * q]);
                acc0[2 * q + 1] = fma2(a_hi, w1.y, acc0[2 * q + 1]);
                acc1[2 * q]     = fma2(b_hi, w1.x, acc1[2 * q]);
                acc1[2 * q + 1] = fma2(b_hi, w1.y, acc1[2 * q + 1]);
            }
        }

        float logitA = 0.f, logitB = 0.f;
#pragma unroll
        for (int q = 0; q < 16; ++q) {
            float2 w = reinterpret_cast<const float2*>(Wa3)[q];
            float2 a = unpk(acc0[q]);
            logitA += fmaxf(a.x, 0.f) * w.x + fmaxf(a.y, 0.f) * w.y;
            float2 b = unpk(acc1[q]);
            logitB += fmaxf(b.x, 0.f) * w.x + fmaxf(b.y, 0.f) * w.y;
        }

        // --- per-n epilogue, twice (u = 0, 1) ---
#pragma unroll
        for (int u = 0; u < 2; ++u) {
            float logit = (u == 0) ? logitA : logitB;

            float m = logit;
#pragma unroll
            for (int off = 16; off; off >>= 1)
                m = fmaxf(m, __shfl_xor_sync(0xffffffffu, m, off));
            if (lane == 0) sMax[warp] = m;
            __syncthreads();
            float gm = sMax[0];
#pragma unroll
            for (int w = 1; w < 16; ++w) gm = fmaxf(gm, sMax[w]);

            float e = __expf(logit - gm);
            float v0 = e, v1 = e * cy.x, v2 = e * cy.y, v3 = e * cy.z, v4 = e * cy.w;
#pragma unroll
            for (int off = 16; off; off >>= 1) {
                v0 += __shfl_xor_sync(0xffffffffu, v0, off);
                v1 += __shfl_xor_sync(0xffffffffu, v1, off);
                v2 += __shfl_xor_sync(0xffffffffu, v2, off);
                v3 += __shfl_xor_sync(0xffffffffu, v3, off);
                v4 += __shfl_xor_sync(0xffffffffu, v4, off);
            }
            if (lane == 0) {
                sRed[warp][0] = v0; sRed[warp][1] = v1; sRed[warp][2] = v2;
                sRed[warp][3] = v3; sRed[warp][4] = v4;
            }
            __syncthreads();
            if (tid < 5) {
                float s = 0.f;
#pragma unroll
                for (int w = 0; w < 16; ++w) s += sRed[w][tid];
                sPool[tid] = s;
            }
            __syncthreads();

            if (tid < 32) {
                float inv = 1.f / sPool[0];
                float a0 = sPool[1] * inv, a1 = sPool[2] * inv;
                float a2 = sPool[3] * inv, a3 = sPool[4] * inv;
                float hp = bp1[tid] + a0 * Wp1[tid] + a1 * Wp1[32 + tid]
                                    + a2 * Wp1[64 + tid] + a3 * Wp1[96 + tid];
                sHp[tid] = fmaxf(hp, 0.f);
            }
            __syncthreads();
            if (tid < 16) {
                float cv = bp2[tid];
#pragma unroll
                for (int k2 = 0; k2 < 32; ++k2) cv += sHp[k2] * Wp2[k2 * 16 + tid];
                g_c[(n + u) * 16 + tid] = cv;
            }
            __syncthreads();
        }
    }
}

// ---------------------------------------------------------------------------
// Gating: block = 16 rows, 256 threads, grid 512.
// Stage B tile (16 rows, 32 j) per warp: lane owns ONE j column ->
// zero Wg2 duplication within the block; rows packed in f32x2 pairs.
__global__ __launch_bounds__(256) void gate_kernel(
    const float* __restrict__ r, const float* __restrict__ rp,
    const float* __restrict__ Wg1, const float* __restrict__ bg1,
    const float* __restrict__ Wg2, const float* __restrict__ bg2,
    const float* __restrict__ Wg3, const float* __restrict__ bg3,
    float* __restrict__ out)
{
    __shared__ float sX[16][25];
    __shared__ __align__(16) float sG1[256 * 16];   // [k][row]
    __shared__ float sPart[8][16];

    const int tid  = threadIdx.x;
    const int lane = tid & 31, warp = tid >> 5;
    const int n0 = blockIdx.x * 16;

    for (int idx = tid; idx < 16 * 24; idx += 256) {
        int row = idx / 24, j = idx % 24;
        int n = n0 + row;
        float v = (j < 4) ? r[n * 4 + j]
                : (j < 8) ? rp[n * 4 + (j - 4)]
                          : g_c[n * 16 + (j - 8)];
        sX[row][j] = v;
    }
    __syncthreads();

    // Stage A: warp w -> k in [32w, 32w+32); lane -> (row = lane&15, khalf = lane>>4)
    {
        const int row = lane & 15, khalf = lane >> 4;
        float x[24];
#pragma unroll
        for (int j = 0; j < 24; ++j) x[j] = sX[row][j];
        const int kbase = warp * 32 + khalf;
#pragma unroll 4
        for (int kk = 0; kk < 16; ++kk) {
            int k = kbase + 2 * kk;
            float a = bg1[k];
#pragma unroll
            for (int j = 0; j < 24; ++j) a += x[j] * Wg1[j * 256 + k];
            sG1[k * 16 + row] = fmaxf(a, 0.f);
        }
    }
    __syncthreads();

    // Stage B: lane's j column; acc[i] = rows (2i, 2i+1) packed
    const int jcol = warp * 32 + lane;

    ULL acc[8];
    {
        ULL b2 = dup2(bg2[jcol]);
#pragma unroll
        for (int i = 0; i < 8; ++i) acc[i] = b2;
    }

    const float* wcol = Wg2 + jcol;          // stride 256 per k (coalesced LDG.32)
    const ulonglong2* gRows = reinterpret_cast<const ulonglong2*>(sG1);

#pragma unroll 8
    for (int k = 0; k < 256; ++k) {
        ULL w2 = dup2(wcol[k * 256]);
        ulonglong2 g01 = gRows[k * 4 + 0];   // rows 0-3 (broadcast LDS.128)
        ulonglong2 g23 = gRows[k * 4 + 1];   // rows 4-7
        ulonglong2 g45 = gRows[k * 4 + 2];   // rows 8-11
        ulonglong2 g67 = gRows[k * 4 + 3];   // rows 12-15
        acc[0] = fma2(g01.x, w2, acc[0]);
        acc[1] = fma2(g01.y, w2, acc[1]);
        acc[2] = fma2(g23.x, w2, acc[2]);
        acc[3] = fma2(g23.y, w2, acc[3]);
        acc[4] = fma2(g45.x, w2, acc[4]);
        acc[5] = fma2(g45.y, w2, acc[5]);
        acc[6] = fma2(g67.x, w2, acc[6]);
        acc[7] = fma2(g67.y, w2, acc[7]);
    }

    // epilogue: relu, * Wg3[jcol], reduce across lanes (j), then across warps
    float w3 = Wg3[jcol];
    float rv[16];
#pragma unroll
    for (int i = 0; i < 8; ++i) {
        float2 a = unpk(acc[i]);
        rv[2 * i]     = fmaxf(a.x, 0.f) * w3;
        rv[2 * i + 1] = fmaxf(a.y, 0.f) * w3;
    }
#pragma unroll
    for (int off = 16; off; off >>= 1) {
#pragma unroll
        for (int i = 0; i < 16; ++i)
            rv[i] += __shfl_xor_sync(0xffffffffu, rv[i], off);
    }
    if (lane == 0) {
#pragma unroll
        for (int i = 0; i < 16; ++i) sPart[warp][i] = rv[i];
    }
    __syncthreads();

    if (tid < 16) {
        float s = bg3[0];
#pragma unroll
        for (int w = 0; w < 8; ++w) s += sPart[w][tid];
        out[n0 + tid] = __expf(s);
    }
}

// ---------------------------------------------------------------------------
extern "C" void kernel_launch(void* const* d_in, const int* in_sizes, int n_in,
                              void* d_out, int out_size) {
    (void)in_sizes; (void)n_in; (void)out_size;
    const float* r   = (const float*)d_in[0];
    const float* rp  = (const float*)d_in[1];
    const float* cx  = (const float*)d_in[2];
    const float* cy  = (const float*)d_in[3];
    const float* Wa1 = (const float*)d_in[4];
    const float* Wa2 = (const float*)d_in[5];
    const float* Wa3 = (const float*)d_in[6];
    const float* Wp1 = (const float*)d_in[7];
    const float* bp1 = (const float*)d_in[8];
    const float* Wp2 = (const float*)d_in[9];
    const float* bp2 = (const float*)d_in[10];
    const float* Wg1 = (const float*)d_in[11];
    const float* bg1 = (const float*)d_in[12];
    const float* Wg2 = (const float*)d_in[13];
    const float* bg2 = (const float*)d_in[14];
    const float* Wg3 = (const float*)d_in[15];
    const float* bg3 = (const float*)d_in[16];
    float* out = (float*)d_out;

    pre_ca<<<16, 512>>>(cx, Wa1);
    pre_qa<<<512, 256>>>(r, Wa1);
    attn_kernel<<<N_TOT / TN, 512>>>(cy, Wa2, Wa3, Wp1, bp1, Wp2, bp2);
    gate_kernel<<<N_TOT / 16, 256>>>(r, rp, Wg1, bg1, Wg2, bg2, Wg3, bg3, out);
}

// round 7
// speedup vs baseline: 17.9874x; 1.1153x over previous
#include <cuda_runtime.h>

typedef unsigned long long ULL;

__device__ __forceinline__ ULL fma2(ULL a, ULL b, ULL c) {
    ULL d;
    asm("fma.rn.f32x2 %0, %1, %2, %3;" : "=l"(d) : "l"(a), "l"(b), "l"(c));
    return d;
}
__device__ __forceinline__ ULL dup2(float x) {
    ULL d;
    asm("mov.b64 %0, {%1, %1};" : "=l"(d) : "f"(x));
    return d;
}
__device__ __forceinline__ float2 unpk(ULL v) {
    float2 r;
    asm("mov.b64 {%0, %1}, %2;" : "=f"(r.x), "=f"(r.y) : "l"(v));
    return r;
}

#define N_TOT 8192
#define TN 8          // n's per attention block (processed as 4 pairs)

// Scratch (static device globals — no allocation)
__device__ __align__(16) float4 g_ca4[8 * 512];   // [k2][p] : h1 cols 4k2..4k2+3
__device__ float g_c[N_TOT * 16];                 // pooled-projection output (N,16)

// ---------------------------------------------------------------------------
// pre_ca: ca[p][j] = cx[p,0]*Wa1[2][j] + cx[p,1]*Wa1[3][j], packed 4 j's per k2.
__global__ void pre_ca(const float* __restrict__ cx, const float* __restrict__ Wa1) {
    int idx = blockIdx.x * blockDim.x + threadIdx.x;   // 4096 = 512p * 8k2
    int p = idx & 511, k2 = idx >> 9;
    float x0 = cx[p * 2 + 0], x1 = cx[p * 2 + 1];
    int j = 4 * k2;
    float4 v;
    v.x = x0 * Wa1[64 + j + 0] + x1 * Wa1[96 + j + 0];
    v.y = x0 * Wa1[64 + j + 1] + x1 * Wa1[96 + j + 1];
    v.z = x0 * Wa1[64 + j + 2] + x1 * Wa1[96 + j + 2];
    v.w = x0 * Wa1[64 + j + 3] + x1 * Wa1[96 + j + 3];
    g_ca4[k2 * 512 + p] = v;
}

// ---------------------------------------------------------------------------
// Attention: block = TN consecutive n's as 4 pairs; thread = p (P=512).
// qa staged in smem; ca via LDG.128; batched pair epilogue (4 barriers/pair).
__global__ __launch_bounds__(512) void attn_kernel(
    const float* __restrict__ r,
    const float* __restrict__ coeff_y,
    const float* __restrict__ Wa1,
    const float* __restrict__ Wa2,
    const float* __restrict__ Wa3,
    const float* __restrict__ Wp1, const float* __restrict__ bp1,
    const float* __restrict__ Wp2, const float* __restrict__ bp2)
{
    __shared__ __align__(16) float sWa2[1024];
    __shared__ __align__(16) float2 sQa[TN][16];  // per n: 16 float2 = 8 float4
    __shared__ float sMaxA[16], sMaxB[16];
    __shared__ float sRed[16][10];
    __shared__ float sPool[2][5];
    __shared__ float sHp[2][32];

    const int tid  = threadIdx.x;
    const int lane = tid & 31, warp = tid >> 5;
    const int n0 = blockIdx.x * TN;

    sWa2[tid]       = Wa2[tid];
    sWa2[tid + 512] = Wa2[tid + 512];
    if (tid < TN * 16) {                     // qa for this block's n's
        int t = tid >> 4, k = tid & 15;
        int n = n0 + t;
        float x0 = r[n * 4 + 0], x1 = r[n * 4 + 1];
        float q0 = x0 * Wa1[2 * k]     + x1 * Wa1[32 + 2 * k];
        float q1 = x0 * Wa1[2 * k + 1] + x1 * Wa1[32 + 2 * k + 1];
        sQa[t][k] = make_float2(q0, q1);
    }
    const float4 cy = reinterpret_cast<const float4*>(coeff_y)[tid];
    __syncthreads();

#pragma unroll 1
    for (int t2 = 0; t2 < TN / 2; ++t2) {
        const int n = n0 + 2 * t2;
        const float4* qaA4 = reinterpret_cast<const float4*>(sQa[2 * t2]);
        const float4* qaB4 = reinterpret_cast<const float4*>(sQa[2 * t2 + 1]);

        ULL acc0[16], acc1[16];
#pragma unroll
        for (int q = 0; q < 16; ++q) { acc0[q] = 0ull; acc1[q] = 0ull; }

#pragma unroll
        for (int k2 = 0; k2 < 8; ++k2) {
            float4 ca  = g_ca4[k2 * 512 + tid];   // coalesced LDG.128, L1-hot
            float4 qaA = qaA4[k2];                // broadcast LDS.128
            float4 qaB = qaB4[k2];
            ULL aLo0 = dup2(fmaxf(qaA.x + ca.x, 0.f));   // h1[4k2]
            ULL aHi0 = dup2(fmaxf(qaA.y + ca.y, 0.f));   // h1[4k2+1]
            ULL aLo1 = dup2(fmaxf(qaA.z + ca.z, 0.f));   // h1[4k2+2]
            ULL aHi1 = dup2(fmaxf(qaA.w + ca.w, 0.f));   // h1[4k2+3]
            ULL bLo0 = dup2(fmaxf(qaB.x + ca.x, 0.f));
            ULL bHi0 = dup2(fmaxf(qaB.y + ca.y, 0.f));
            ULL bLo1 = dup2(fmaxf(qaB.z + ca.z, 0.f));
            ULL bHi1 = dup2(fmaxf(qaB.w + ca.w, 0.f));
            {   // Wa2 rows 4k2, 4k2+1
                const ulonglong2* r0 = reinterpret_cast<const ulonglong2*>(sWa2 + 128 * k2);
#pragma unroll
                for (int q = 0; q < 8; ++q) {
                    ulonglong2 w0 = r0[q];
                    ulonglong2 w1 = r0[q + 8];
                    acc0[2 * q]     = fma2(aLo0, w0.x, acc0[2 * q]);
                    acc0[2 * q + 1] = fma2(aLo0, w0.y, acc0[2 * q + 1]);
                    acc1[2 * q]     = fma2(bLo0, w0.x, acc1[2 * q]);
                    acc1[2 * q + 1] = fma2(bLo0, w0.y, acc1[2 * q + 1]);
                    acc0[2 * q]     = fma2(aHi0, w1.x, acc0[2 * q]);
                    acc0[2 * q + 1] = fma2(aHi0, w1.y, acc0[2 * q + 1]);
                    acc1[2 * q]     = fma2(bHi0, w1.x, acc1[2 * q]);
                    acc1[2 * q + 1] = fma2(bHi0, w1.y, acc1[2 * q + 1]);
                }
            }
            {   // Wa2 rows 4k2+2, 4k2+3
                const ulonglong2* r1 = reinterpret_cast<const ulonglong2*>(sWa2 + 128 * k2 + 64);
#pragma unroll
                for (int q = 0; q < 8; ++q) {
                    ulonglong2 w0 = r1[q];
                    ulonglong2 w1 = r1[q + 8];
                    acc0[2 * q]     = fma2(aLo1, w0.x, acc0[2 * q]);
                    acc0[2 * q + 1] = fma2(aLo1, w0.y, acc0[2 * q + 1]);
                    acc1[2 * q]     = fma2(bLo1, w0.x, acc1[2 * q]);
                    acc1[2 * q + 1] = fma2(bLo1, w0.y, acc1[2 * q + 1]);
                    acc0[2 * q]     = fma2(aHi1, w1.x, acc0[2 * q]);
                    acc0[2 * q + 1] = fma2(aHi1, w1.y, acc0[2 * q + 1]);
                    acc1[2 * q]     = fma2(bHi1, w1.x, acc1[2 * q]);
                    acc1[2 * q + 1] = fma2(bHi1, w1.y, acc1[2 * q + 1]);
                }
            }
        }

        float logitA = 0.f, logitB = 0.f;
#pragma unroll
        for (int q = 0; q < 16; ++q) {
            float2 w = reinterpret_cast<const float2*>(Wa3)[q];
            float2 a = unpk(acc0[q]);
            logitA += fmaxf(a.x, 0.f) * w.x + fmaxf(a.y, 0.f) * w.y;
            float2 b = unpk(acc1[q]);
            logitB += fmaxf(b.x, 0.f) * w.x + fmaxf(b.y, 0.f) * w.y;
        }

        // ===== batched epilogue for the pair =====
        float mA = logitA, mB = logitB;
#pragma unroll
        for (int off = 16; off; off >>= 1) {
            mA = fmaxf(mA, __shfl_xor_sync(0xffffffffu, mA, off));
            mB = fmaxf(mB, __shfl_xor_sync(0xffffffffu, mB, off));
        }
        if (lane == 0) { sMaxA[warp] = mA; sMaxB[warp] = mB; }
        __syncthreads();                                        // B1
        float gmA = sMaxA[0], gmB = sMaxB[0];
#pragma unroll
        for (int w = 1; w < 16; ++w) {
            gmA = fmaxf(gmA, sMaxA[w]);
            gmB = fmaxf(gmB, sMaxB[w]);
        }

        float eA = __expf(logitA - gmA);
        float eB = __expf(logitB - gmB);
        float vA0 = eA, vA1 = eA * cy.x, vA2 = eA * cy.y, vA3 = eA * cy.z, vA4 = eA * cy.w;
        float vB0 = eB, vB1 = eB * cy.x, vB2 = eB * cy.y, vB3 = eB * cy.z, vB4 = eB * cy.w;
#pragma unroll
        for (int off = 16; off; off >>= 1) {
            vA0 += __shfl_xor_sync(0xffffffffu, vA0, off);
            vB0 += __shfl_xor_sync(0xffffffffu, vB0, off);
            vA1 += __shfl_xor_sync(0xffffffffu, vA1, off);
            vB1 += __shfl_xor_sync(0xffffffffu, vB1, off);
            vA2 += __shfl_xor_sync(0xffffffffu, vA2, off);
            vB2 += __shfl_xor_sync(0xffffffffu, vB2, off);
            vA3 += __shfl_xor_sync(0xffffffffu, vA3, off);
            vB3 += __shfl_xor_sync(0xffffffffu, vB3, off);
            vA4 += __shfl_xor_sync(0xffffffffu, vA4, off);
            vB4 += __shfl_xor_sync(0xffffffffu, vB4, off);
        }
        if (lane == 0) {
            sRed[warp][0] = vA0; sRed[warp][1] = vA1; sRed[warp][2] = vA2;
            sRed[warp][3] = vA3; sRed[warp][4] = vA4;
            sRed[warp][5] = vB0; sRed[warp][6] = vB1; sRed[warp][7] = vB2;
            sRed[warp][8] = vB3; sRed[warp][9] = vB4;
        }
        __syncthreads();                                        // B2
        if (tid < 10) {
            float s = 0.f;
#pragma unroll
            for (int w = 0; w < 16; ++w) s += sRed[w][tid];
            sPool[tid / 5][tid % 5] = s;
        }
        __syncthreads();                                        // B3
        if (tid < 64) {
            int u = tid >> 5, j = tid & 31;
            float inv = 1.f / sPool[u][0];
            float a0 = sPool[u][1] * inv, a1 = sPool[u][2] * inv;
            float a2 = sPool[u][3] * inv, a3 = sPool[u][4] * inv;
            float hp = bp1[j] + a0 * Wp1[j] + a1 * Wp1[32 + j]
                              + a2 * Wp1[64 + j] + a3 * Wp1[96 + j];
            sHp[u][j] = fmaxf(hp, 0.f);
        }
        __syncthreads();                                        // B4
        if (tid < 32) {
            int u = tid >> 4, j = tid & 15;
            float cv = bp2[j];
#pragma unroll
            for (int k = 0; k < 32; ++k) cv += sHp[u][k] * Wp2[k * 16 + j];
            g_c[(n + u) * 16 + j] = cv;
        }
        // no trailing barrier needed: every reused buffer (sMax*, sRed, sPool,
        // sHp) is next WRITTEN only after a barrier that follows its last read.
    }
}

// ---------------------------------------------------------------------------
// Gating: block = 16 rows, 256 threads, grid 512. (unchanged from R6)
__global__ __launch_bounds__(256) void gate_kernel(
    const float* __restrict__ r, const float* __restrict__ rp,
    const float* __restrict__ Wg1, const float* __restrict__ bg1,
    const float* __restrict__ Wg2, const float* __restrict__ bg2,
    const float* __restrict__ Wg3, const float* __restrict__ bg3,
    float* __restrict__ out)
{
    __shared__ float sX[16][25];
    __shared__ __align__(16) float sG1[256 * 16];   // [k][row]
    __shared__ float sPart[8][16];

    const int tid  = threadIdx.x;
    const int lane = tid & 31, warp = tid >> 5;
    const int n0 = blockIdx.x * 16;

    for (int idx = tid; idx < 16 * 24; idx += 256) {
        int row = idx / 24, j = idx % 24;
        int n = n0 + row;
        float v = (j < 4) ? r[n * 4 + j]
                : (j < 8) ? rp[n * 4 + (j - 4)]
                          : g_c[n * 16 + (j - 8)];
        sX[row][j] = v;
    }
    __syncthreads();

    {
        const int row = lane & 15, khalf = lane >> 4;
        float x[24];
#pragma unroll
        for (int j = 0; j < 24; ++j) x[j] = sX[row][j];
        const int kbase = warp * 32 + khalf;
#pragma unroll 4
        for (int kk = 0; kk < 16; ++kk) {
            int k = kbase + 2 * kk;
            float a = bg1[k];
#pragma unroll
            for (int j = 0; j < 24; ++j) a += x[j] * Wg1[j * 256 + k];
            sG1[k * 16 + row] = fmaxf(a, 0.f);
        }
    }
    __syncthreads();

    const int jcol = warp * 32 + lane;

    ULL acc[8];
    {
        ULL b2 = dup2(bg2[jcol]);
#pragma unroll
        for (int i = 0; i < 8; ++i) acc[i] = b2;
    }

    const float* wcol = Wg2 + jcol;
    const ulonglong2* gRows = reinterpret_cast<const ulonglong2*>(sG1);

#pragma unroll 8
    for (int k = 0; k < 256; ++k) {
        ULL w2 = dup2(wcol[k * 256]);
        ulonglong2 g01 = gRows[k * 4 + 0];
        ulonglong2 g23 = gRows[k * 4 + 1];
        ulonglong2 g45 = gRows[k * 4 + 2];
        ulonglong2 g67 = gRows[k * 4 + 3];
        acc[0] = fma2(g01.x, w2, acc[0]);
        acc[1] = fma2(g01.y, w2, acc[1]);
        acc[2] = fma2(g23.x, w2, acc[2]);
        acc[3] = fma2(g23.y, w2, acc[3]);
        acc[4] = fma2(g45.x, w2, acc[4]);
        acc[5] = fma2(g45.y, w2, acc[5]);
        acc[6] = fma2(g67.x, w2, acc[6]);
        acc[7] = fma2(g67.y, w2, acc[7]);
    }

    float w3 = Wg3[jcol];
    float rv[16];
#pragma unroll
    for (int i = 0; i < 8; ++i) {
        float2 a = unpk(acc[i]);
        rv[2 * i]     = fmaxf(a.x, 0.f) * w3;
        rv[2 * i + 1] = fmaxf(a.y, 0.f) * w3;
    }
#pragma unroll
    for (int off = 16; off; off >>= 1) {
#pragma unroll
        for (int i = 0; i < 16; ++i)
            rv[i] += __shfl_xor_sync(0xffffffffu, rv[i], off);
    }
    if (lane == 0) {
#pragma unroll
        for (int i = 0; i < 16; ++i) sPart[warp][i] = rv[i];
    }
    __syncthreads();

    if (tid < 16) {
        float s = bg3[0];
#pragma unroll
        for (int w = 0; w < 8; ++w) s += sPart[w][tid];
        out[n0 + tid] = __expf(s);
    }
}

// ---------------------------------------------------------------------------
extern "C" void kernel_launch(void* const* d_in, const int* in_sizes, int n_in,
                              void* d_out, int out_size) {
    (void)in_sizes; (void)n_in; (void)out_size;
    const float* r   = (const float*)d_in[0];
    const float* rp  = (const float*)d_in[1];
    const float* cx  = (const float*)d_in[2];
    const float* cy  = (const float*)d_in[3];
    const float* Wa1 = (const float*)d_in[4];
    const float* Wa2 = (const float*)d_in[5];
    const float* Wa3 = (const float*)d_in[6];
    const float* Wp1 = (const float*)d_in[7];
    const float* bp1 = (const float*)d_in[8];
    const float* Wp2 = (const float*)d_in[9];
    const float* bp2 = (const float*)d_in[10];
    const float* Wg1 = (const float*)d_in[11];
    const float* bg1 = (const float*)d_in[12];
    const float* Wg2 = (const float*)d_in[13];
    const float* bg2 = (const float*)d_in[14];
    const float* Wg3 = (const float*)d_in[15];
    const float* bg3 = (const float*)d_in[16];
    float* out = (float*)d_out;

    pre_ca<<<8, 512>>>(cx, Wa1);
    attn_kernel<<<N_TOT / TN, 512>>>(r, cy, Wa1, Wa2, Wa3, Wp1, bp1, Wp2, bp2);
    gate_kernel<<<N_TOT / 16, 256>>>(r, rp, Wg1, bg1, Wg2, bg2, Wg3, bg3, out);
}